// round 6
// baseline (speedup 1.0000x reference)
#include <cuda_runtime.h>
#include <math.h>

#define STEPF   0.1f
#define MAXL    1024
#define MAXNS   64
#define DELAY_N 30
#define TPB     64
#define PPT     2            // pixels per thread

__device__ float2 g_aif2[MAXL];   // AIF duplicated into both lanes
__device__ int    g_idx[MAXNS];
__device__ int    g_L;

typedef unsigned long long u64;

__device__ __forceinline__ u64 fma2(u64 a, u64 b, u64 c) {
    u64 d;
    asm("fma.rn.f32x2 %0, %1, %2, %3;" : "=l"(d) : "l"(a), "l"(b), "l"(c));
    return d;
}
__device__ __forceinline__ u64 pack2(float lo, float hi) {
    u64 d; asm("mov.b64 %0, {%1, %2};" : "=l"(d) : "f"(lo), "f"(hi)); return d;
}
__device__ __forceinline__ void unpack2(u64 v, float& lo, float& hi) {
    asm("mov.b64 {%0, %1}, %2;" : "=f"(lo), "=f"(hi) : "l"(v));
}

// ---------------------------------------------------------------------------
// Prep (1 block): stage 50-pt inputs in shared, then build fine-grid AIF
// (interp + 3s delay) and searchsorted sample indices. All searches hit smem.
// ---------------------------------------------------------------------------
__global__ void dce_prep_kernel(const float* __restrict__ sample_time,
                                const float* __restrict__ Cp, int ns)
{
    __shared__ float s_st[MAXNS];
    __shared__ float s_cp[MAXNS];

    for (int j = threadIdx.x; j < ns && j < MAXNS; j += blockDim.x) {
        s_st[j] = sample_time[j];
        s_cp[j] = Cp[j];
    }
    __syncthreads();

    double t_end = (double)s_st[ns - 1];
    int L = (int)llrint(t_end / 0.1) + 1;
    if (L > MAXL) L = MAXL;
    if (threadIdx.x == 0) g_L = L;

    for (int i = threadIdx.x; i < L; i += blockDim.x) {
        float val = 0.f;
        if (i >= DELAY_N) {
            const float t = (float)(i - DELAY_N) * STEPF;
            if (t <= s_st[0]) {
                val = s_cp[0];
            } else if (t >= s_st[ns - 1]) {
                val = s_cp[ns - 1];
            } else {
                int lo = 0, hi = ns - 1;
                while (lo + 1 < hi) {
                    int mid = (lo + hi) >> 1;
                    if (s_st[mid] <= t) lo = mid; else hi = mid;
                }
                const float x0 = s_st[lo], x1 = s_st[lo + 1];
                val = s_cp[lo] + (t - x0) * (s_cp[lo + 1] - s_cp[lo]) / (x1 - x0);
            }
        }
        g_aif2[i] = make_float2(val, val);
    }

    for (int j = threadIdx.x; j < ns && j < MAXNS; j += blockDim.x) {
        const float st = s_st[j];
        int lo = 0, hi = L;
        while (lo < hi) {
            int mid = (lo + hi) >> 1;
            if ((float)mid * STEPF < st) lo = mid + 1; else hi = mid; // same IEEE ops as jnp
        }
        g_idx[j] = lo < (L - 1) ? lo : (L - 1);
    }
}

// ---------------------------------------------------------------------------
// Main: 2 pixels/thread, packed (Sm,Sp) bi-exponential recurrence + SPGR
// ---------------------------------------------------------------------------
__global__ void __launch_bounds__(TPB)
dce_main_kernel(const float* __restrict__ param,
                float* __restrict__ out, int npix, int ns)
{
    __shared__ float2 s_aif2[MAXL];
    __shared__ int    s_idx[MAXNS];

    const int tid = threadIdx.x;
    const int L = g_L;
    for (int i = tid; i < L; i += TPB) s_aif2[i] = g_aif2[i];
    for (int j = tid; j < ns && j < MAXNS; j += TPB) s_idx[j] = g_idx[j];
    __syncthreads();

    const int base = blockIdx.x * (TPB * PPT) + tid;

    float ve[PPT], vp[PPT], cm[PPT], cpc[PPT], inv_she[PPT], inv_shp[PPT];
    u64 S[PPT], R[PPT];
    bool valid[PPT];

    #pragma unroll
    for (int k = 0; k < PPT; ++k) {
        int pix = base + k * TPB;
        valid[k] = pix < npix;
        int p = valid[k] ? pix : 0;

        const float vek = param[p];
        const float vpk = param[npix + p];
        const float fpp = param[2 * npix + p];
        const float ps  = param[3 * npix + p];
        ve[k] = vek; vp[k] = vpk;

        const float Te = vek / ps;
        const float T  = (vpk + vek) / fpp;
        const float Tc = vpk / fpp;
        const float s  = T + Te;
        const float disc = sqrtf(fmaxf(s * s - 4.f * Tc * Te, 0.f));
        const float inv2 = 1.f / (2.f * Tc * Te);
        const float thp = (s + disc) * inv2;
        const float thm = (s - disc) * inv2;

        const float rm = expf(-thm * STEPF);   // compounds over L steps: precise
        const float rp = expf(-thp * STEPF);
        R[k] = pack2(rm, rp);
        S[k] = 0ull;

        const float Lf  = (float)L;
        const float SEm = (-expm1f(-thm * STEPF * Lf)) / (-expm1f(-thm * STEPF));
        const float SEp = (-expm1f(-thp * STEPF * Lf)) / (-expm1f(-thp * STEPF));

        cm[k]  = 1.f - Te * thm;
        cpc[k] = Te * thp - 1.f;
        inv_she[k] = 1.f / (SEm - SEp);
        inv_shp[k] = 1.f / fmaf(cm[k], SEm, cpc[k] * SEp);
    }

    // SPGR constants
    const float cosfa = 0.98480775301220806f;   // cos(10 deg)
    const float E1    = expf(-0.00487f);
    const float M0t   = 100.f * (1.f - cosfa * E1) / (1.f - E1);
    const float bse   = 100.f - M0t * (1.f - E1) / (1.f - E1 * cosfa);

    const u64* __restrict__ aifu = reinterpret_cast<const u64*>(s_aif2);

    float* __restrict__ orow = out + base;   // advances by npix each sample

    int m = 0;
    for (int j = 0; j < ns; ++j) {
        const int target = s_idx[j];
        const int n = target - m + 1;
        #pragma unroll 4
        for (int kk = 0; kk < n; ++kk) {
            const u64 a = aifu[m + kk];
            S[0] = fma2(S[0], R[0], a);
            S[1] = fma2(S[1], R[1], a);
        }
        m = target + 1;

        #pragma unroll
        for (int k = 0; k < PPT; ++k) {
            float Sm, Sp;
            unpack2(S[k], Sm, Sp);
            const float ce   = inv_she[k] * (Sm - Sp);
            const float cpv  = inv_shp[k] * fmaf(cm[k], Sm, cpc[k] * Sp);
            const float conc = vp[k] * cpv + ve[k] * ce;
            const float E1CA = __expf(-0.00487f * fmaf(4.3f, conc, 1.0f));
            const float sig  = __fdividef(M0t * (1.f - E1CA), 1.f - E1CA * cosfa) + bse;
            if (valid[k]) orow[k * TPB] = sig;
        }
        orow += npix;
    }
}

extern "C" void kernel_launch(void* const* d_in, const int* in_sizes, int n_in,
                              void* d_out, int out_size)
{
    const float* param       = (const float*)d_in[0];
    const float* sample_time = (const float*)d_in[1];
    const float* Cp          = (const float*)d_in[2];
    float* out = (float*)d_out;

    const int ns   = in_sizes[1];
    const int npix = in_sizes[0] / 4;

    dce_prep_kernel<<<1, 128>>>(sample_time, Cp, ns);

    const int pix_per_block = TPB * PPT;
    const int blocks = (npix + pix_per_block - 1) / pix_per_block;
    dce_main_kernel<<<blocks, TPB>>>(param, out, npix, ns);
}

// round 7
// speedup vs baseline: 1.1021x; 1.1021x over previous
#include <cuda_runtime.h>
#include <math.h>

#define STEPF   0.1f
#define MAXL    2048
#define MAXNS   64
#define MAXNP   128
#define DELAY_N 30
#define TPB     64

__device__ float  g_aif[MAXL];
__device__ float2 g_pieces[MAXNP];
__device__ int    g_idx[MAXNS];
__device__ int    g_L;
__device__ int    g_aligned;

typedef unsigned long long u64;

__device__ __forceinline__ u64 fma2(u64 a, u64 b, u64 c) {
    u64 d; asm("fma.rn.f32x2 %0, %1, %2, %3;" : "=l"(d) : "l"(a), "l"(b), "l"(c)); return d;
}
__device__ __forceinline__ u64 mul2(u64 a, u64 b) {
    u64 d; asm("mul.rn.f32x2 %0, %1, %2;" : "=l"(d) : "l"(a), "l"(b)); return d;
}
__device__ __forceinline__ u64 pack2(float lo, float hi) {
    u64 d; asm("mov.b64 %0, {%1, %2};" : "=l"(d) : "f"(lo), "f"(hi)); return d;
}
__device__ __forceinline__ u64 dup2(float v) { return pack2(v, v); }
__device__ __forceinline__ void unpack2(u64 v, float& lo, float& hi) {
    asm("mov.b64 {%0, %1}, %2;" : "=f"(lo), "=f"(hi) : "l"(v));
}
__device__ __forceinline__ float rcpf(float x) {
    float r; asm("rcp.approx.f32 %0, %1;" : "=f"(r) : "f"(x)); return r;
}

__device__ __forceinline__ float interp_at(float t, const float* st, const float* cp, int ns) {
    if (t <= st[0]) return cp[0];
    if (t >= st[ns - 1]) return cp[ns - 1];
    int lo = 0, hi = ns - 1;
    while (lo + 1 < hi) { int mid = (lo + hi) >> 1; if (st[mid] <= t) lo = mid; else hi = mid; }
    return cp[lo] + (t - st[lo]) * (cp[lo + 1] - cp[lo]) / (st[lo + 1] - st[lo]);
}

__global__ void dce_prep_kernel(const float* __restrict__ sample_time,
                                const float* __restrict__ Cp, int ns)
{
    __shared__ float s_st[MAXNS], s_cp[MAXNS], s_av[MAXNP + 1];
    __shared__ int s_ok;
    const int tid = threadIdx.x;
    if (tid == 0) s_ok = 1;
    for (int j = tid; j < ns && j < MAXNS; j += blockDim.x) { s_st[j] = sample_time[j]; s_cp[j] = Cp[j]; }
    __syncthreads();

    const int Ltrue = (int)llrint((double)s_st[ns - 1] / 0.1) + 1;
    const int L = Ltrue < MAXL ? Ltrue : MAXL;
    if (tid == 0) g_L = L;

    for (int i = tid; i < L; i += blockDim.x)
        g_aif[i] = (i >= DELAY_N) ? interp_at((float)(i - DELAY_N) * STEPF, s_st, s_cp, ns) : 0.f;

    for (int j = tid; j < ns && j < MAXNS; j += blockDim.x) {
        const float st = s_st[j];
        int lo = 0, hi = L;
        while (lo < hi) { int mid = (lo + hi) >> 1; if ((float)mid * STEPF < st) lo = mid + 1; else hi = mid; }
        lo = lo < (L - 1) ? lo : (L - 1);
        g_idx[j] = lo;
        if (lo != 12 * j) s_ok = 0;
    }
    __syncthreads();

    const int NP = 2 * ns - 7;
    int aligned = s_ok && ns >= 5 && ns <= MAXNS && NP < MAXNP && Ltrue == 12 * (ns - 1) + 1;
    if (aligned) {
        for (int i = tid; i <= NP; i += blockDim.x)
            s_av[i] = interp_at((float)(6 * i) * STEPF, s_st, s_cp, ns);
        __syncthreads();
        for (int i = tid; i < NP; i += blockDim.x)
            g_pieces[i] = make_float2(s_av[i], (s_av[i + 1] - s_av[i]) * (1.f / 6.f));
    }
    if (tid == 0) g_aligned = aligned;
}

__global__ void __launch_bounds__(TPB)
dce_main_kernel(const float* __restrict__ param, float* __restrict__ out, int npix, int ns)
{
    __shared__ __align__(16) float2 s_p[MAXNP];
    __shared__ float s_aif[MAXL];
    __shared__ int   s_idx[MAXNS];

    const int tid = threadIdx.x;
    const int aligned = g_aligned;
    const int L  = g_L;
    const int NP = 2 * ns - 7;

    if (aligned) {
        for (int i = tid; i < NP; i += TPB) s_p[i] = g_pieces[i];
    } else {
        for (int i = tid; i < L; i += TPB) s_aif[i] = g_aif[i];
        for (int j = tid; j < ns && j < MAXNS; j += TPB) s_idx[j] = g_idx[j];
    }
    __syncthreads();

    const int pix = blockIdx.x * TPB + tid;
    if (pix >= npix) return;

    const float ve  = param[pix];
    const float vp  = param[npix + pix];
    const float fpp = param[2 * npix + pix];
    const float ps  = param[3 * npix + pix];

    const float Te = ve / ps;
    const float T  = (vp + ve) / fpp;
    const float Tc = vp / fpp;
    const float s  = T + Te;
    const float disc = sqrtf(fmaxf(s * s - 4.f * Tc * Te, 0.f));
    const float inv2 = 1.f / (2.f * Tc * Te);
    const float thp = (s + disc) * inv2;
    const float thm = (s - disc) * inv2;

    const float rm = expf(-thm * STEPF);
    const float rp = expf(-thp * STEPF);
    const float Lf = (float)L;
    const float SEm = (-expm1f(-thm * STEPF * Lf)) / (-expm1f(-thm * STEPF));
    const float SEp = (-expm1f(-thp * STEPF * Lf)) / (-expm1f(-thp * STEPF));

    const float cmv = 1.f - Te * thm;
    const float cpc = Te * thp - 1.f;
    const float inv_she = 1.f / (SEm - SEp);
    const float inv_shp = 1.f / fmaf(cmv, SEm, cpc * SEp);

    // conc = alpha*Sm + beta*Sp; fold z = -TR*R1CA*conc into packed coeffs
    const float alpha = vp * inv_shp * cmv + ve * inv_she;
    const float beta  = vp * inv_shp * cpc - ve * inv_she;
    const float Kz    = -(0.00487f * 4.3f);
    const u64   ZAB   = pack2(Kz * alpha, Kz * beta);

    const float cosfa = 0.98480775301220806f;
    const float E1    = expf(-0.00487f);
    const float M0t   = 100.f * (1.f - cosfa * E1) / (1.f - E1);
    const float bse   = 100.f - M0t * (1.f - E1) / (1.f - E1 * cosfa);
    const float c0 = E1, c1 = E1, c2 = E1 * 0.5f, c3 = E1 * (1.f / 6.f);

    const u64 R = pack2(rm, rp);

    #define SIG_OF(Sv, dst) do {                                           \
        float _zl, _zh; unpack2(mul2((Sv), ZAB), _zl, _zh);                \
        const float _z = _zl + _zh;                                        \
        const float _e = fmaf(fmaf(fmaf(_z, c3, c2), _z, c1), _z, c0);     \
        (dst) = fmaf(fmaf(-M0t, _e, M0t), rcpf(fmaf(-cosfa, _e, 1.f)), bse); \
    } while (0)

    float* optr = out + pix;
    const size_t stp = (size_t)npix;

    if (aligned) {
        // Horner-built per-pixel piece constants
        const u64 ONE = pack2(1.f, 1.f);
        const u64 R2 = mul2(R, R), R6 = mul2(mul2(R2, R2), R2);
        u64 G6 = fma2(R, ONE, ONE);
        G6 = fma2(G6, R, ONE); G6 = fma2(G6, R, ONE);
        G6 = fma2(G6, R, ONE); G6 = fma2(G6, R, ONE);          // 1+r+..+r^5
        u64 H6 = fma2(R, ONE, pack2(2.f, 2.f));
        H6 = fma2(H6, R, pack2(3.f, 3.f)); H6 = fma2(H6, R, pack2(4.f, 4.f));
        H6 = fma2(H6, R, pack2(5.f, 5.f)); H6 = fma2(H6, R, pack2(6.f, 6.f)); // Σ i·r^(6-i)

        float sig0; SIG_OF(0ull, sig0);                        // j=0..2: S=0
        optr[0] = sig0; optr[stp] = sig0; optr[2 * stp] = sig0;
        optr += 3 * stp;

        u64 S = dup2(s_p[0].x);                                // S at fine index 30 = aif[30]
        const float4* __restrict__ pp4 = reinterpret_cast<const float4*>(s_p);
        const int npairs = ns - 4;
        for (int k = 0; k < npairs; ++k) {
            const float4 pq = pp4[k];                          // pieces 2k, 2k+1
            S = fma2(S, R6, fma2(dup2(pq.y), H6, mul2(dup2(pq.x), G6)));
            float sig; SIG_OF(S, sig);
            *optr = sig; optr += stp;
            S = fma2(S, R6, fma2(dup2(pq.w), H6, mul2(dup2(pq.z), G6)));
        }
        const float2 pf = s_p[NP - 1];
        S = fma2(S, R6, fma2(dup2(pf.y), H6, mul2(dup2(pf.x), G6)));
        float sigl; SIG_OF(S, sigl);
        *optr = sigl;
    } else {
        // fallback: proven unit-step recurrence
        u64 S = 0ull;
        int m = 0;
        for (int j = 0; j < ns; ++j) {
            const int target = s_idx[j];
            #pragma unroll 4
            for (; m <= target; ++m) {
                const float a = s_aif[m];
                S = fma2(S, R, dup2(a));
            }
            float sig; SIG_OF(S, sig);
            *optr = sig; optr += stp;
        }
    }
    #undef SIG_OF
}

extern "C" void kernel_launch(void* const* d_in, const int* in_sizes, int n_in,
                              void* d_out, int out_size)
{
    const float* param       = (const float*)d_in[0];
    const float* sample_time = (const float*)d_in[1];
    const float* Cp          = (const float*)d_in[2];
    float* out = (float*)d_out;

    const int ns   = in_sizes[1];
    const int npix = in_sizes[0] / 4;

    dce_prep_kernel<<<1, 128>>>(sample_time, Cp, ns);
    dce_main_kernel<<<(npix + TPB - 1) / TPB, TPB>>>(param, out, npix, ns);
}

// round 8
// speedup vs baseline: 1.7508x; 1.5886x over previous
#include <cuda_runtime.h>
#include <math.h>

#define STEPF   0.1f
#define MAXL    2048
#define MAXNS   64
#define MAXNP   128
#define DELAY_N 30
#define TPB     64

typedef unsigned long long u64;

__device__ float  g_aif[MAXL];
__device__ float4 g_p4[MAXNP];     // per piece: (A, A, slope, slope)
__device__ float2 g_ex[MAXNS];     // per output: dup'd aif[12j+1]
__device__ int    g_idx[MAXNS];
__device__ int    g_L;
__device__ int    g_aligned;
__device__ u64    g_dmask;

__device__ __forceinline__ u64 fma2(u64 a, u64 b, u64 c) {
    u64 d; asm("fma.rn.f32x2 %0, %1, %2, %3;" : "=l"(d) : "l"(a), "l"(b), "l"(c)); return d;
}
__device__ __forceinline__ u64 mul2(u64 a, u64 b) {
    u64 d; asm("mul.rn.f32x2 %0, %1, %2;" : "=l"(d) : "l"(a), "l"(b)); return d;
}
__device__ __forceinline__ u64 pack2(float lo, float hi) {
    u64 d; asm("mov.b64 %0, {%1, %2};" : "=l"(d) : "f"(lo), "f"(hi)); return d;
}
__device__ __forceinline__ u64 dup2(float v) { return pack2(v, v); }
__device__ __forceinline__ void unpack2(u64 v, float& lo, float& hi) {
    asm("mov.b64 {%0, %1}, %2;" : "=f"(lo), "=f"(hi) : "l"(v));
}
__device__ __forceinline__ float rcpf(float x) {
    float r; asm("rcp.approx.f32 %0, %1;" : "=f"(r) : "f"(x)); return r;
}

__device__ __forceinline__ float interp_at(float t, const float* st, const float* cp, int ns) {
    if (t <= st[0]) return cp[0];
    if (t >= st[ns - 1]) return cp[ns - 1];
    int lo = 0, hi = ns - 1;
    while (lo + 1 < hi) { int mid = (lo + hi) >> 1; if (st[mid] <= t) lo = mid; else hi = mid; }
    return cp[lo] + (t - st[lo]) * (cp[lo + 1] - cp[lo]) / (st[lo + 1] - st[lo]);
}

// ---------------------------------------------------------------------------
__global__ void dce_prep_kernel(const float* __restrict__ sample_time,
                                const float* __restrict__ Cp, int ns)
{
    __shared__ float s_st[MAXNS], s_cp[MAXNS], s_av[MAXNP + 1];
    __shared__ int s_ok;
    __shared__ unsigned int s_dm[2];
    const int tid = threadIdx.x;
    if (tid == 0) { s_ok = 1; s_dm[0] = 0; s_dm[1] = 0; }
    for (int j = tid; j < ns && j < MAXNS; j += blockDim.x) { s_st[j] = sample_time[j]; s_cp[j] = Cp[j]; }
    __syncthreads();

    const int Ltrue = (int)llrint((double)s_st[ns - 1] / 0.1) + 1;
    const int L = Ltrue < MAXL ? Ltrue : MAXL;
    if (tid == 0) g_L = L;

    // exact searchsorted (identical IEEE ops to jnp) + d_j classification
    for (int j = tid; j < ns && j < MAXNS; j += blockDim.x) {
        const float st = s_st[j];
        int lo = 0, hi = L;
        while (lo < hi) { int mid = (lo + hi) >> 1; if ((float)mid * STEPF < st) lo = mid + 1; else hi = mid; }
        lo = lo < (L - 1) ? lo : (L - 1);
        g_idx[j] = lo;
        const int d = lo - 12 * j;
        if (d < 0 || d > 1) s_ok = 0;
        else if (d == 1) atomicOr(&s_dm[j >> 5], 1u << (j & 31));
    }
    __syncthreads();

    const int NP = 2 * ns - 7;
    const int aligned = s_ok && ns >= 5 && ns <= MAXNS && NP < MAXNP && Ltrue == 12 * (ns - 1) + 1;
    if (tid == 0) { g_aligned = aligned; g_dmask = ((u64)s_dm[1] << 32) | (u64)s_dm[0]; }

    if (aligned) {
        // boundary values at fine index 30+6i (t = (6i)*0.1f), i = 0..NP
        for (int i = tid; i <= NP; i += blockDim.x)
            s_av[i] = interp_at((float)(6 * i) * STEPF, s_st, s_cp, ns);
        __syncthreads();
        for (int i = tid; i < NP; i += blockDim.x) {
            const float A = s_av[i];
            const float sl = (s_av[i + 1] - A) * (1.f / 6.f);
            g_p4[i] = make_float4(A, A, sl, sl);
        }
        // extra emit values aif[12j+1] for the d_j=1 case
        for (int j = tid; j < ns && j < MAXNS; j += blockDim.x) {
            const int m = 12 * j + 1;
            float v = 0.f;
            if (m >= DELAY_N && m < L) v = interp_at((float)(m - DELAY_N) * STEPF, s_st, s_cp, ns);
            g_ex[j] = make_float2(v, v);
        }
    } else {
        for (int i = tid; i < L; i += blockDim.x)
            g_aif[i] = (i >= DELAY_N) ? interp_at((float)(i - DELAY_N) * STEPF, s_st, s_cp, ns) : 0.f;
    }
}

// ---------------------------------------------------------------------------
__global__ void __launch_bounds__(TPB)
dce_main_kernel(const float* __restrict__ param, float* __restrict__ out, int npix, int ns)
{
    __shared__ __align__(16) float4 s_p4[MAXNP];
    __shared__ __align__(8)  float2 s_ex[MAXNS];
    __shared__ float s_aif[MAXL];
    __shared__ int   s_idx[MAXNS];

    const int tid = threadIdx.x;
    const int aligned = g_aligned;
    const int L  = g_L;
    const int NP = 2 * ns - 7;

    if (aligned) {
        for (int i = tid; i < NP; i += TPB) s_p4[i] = g_p4[i];
        for (int j = tid; j < ns && j < MAXNS; j += TPB) s_ex[j] = g_ex[j];
    } else {
        for (int i = tid; i < L; i += TPB) s_aif[i] = g_aif[i];
        for (int j = tid; j < ns && j < MAXNS; j += TPB) s_idx[j] = g_idx[j];
    }
    __syncthreads();

    const int pix = blockIdx.x * TPB + tid;
    if (pix >= npix) return;

    const float ve  = param[pix];
    const float vp  = param[npix + pix];
    const float fpp = param[2 * npix + pix];
    const float ps  = param[3 * npix + pix];

    const float Te = ve / ps;
    const float T  = (vp + ve) / fpp;
    const float Tc = vp / fpp;
    const float s  = T + Te;
    const float disc = sqrtf(fmaxf(s * s - 4.f * Tc * Te, 0.f));
    const float inv2 = 1.f / (2.f * Tc * Te);
    const float thp = (s + disc) * inv2;
    const float thm = (s - disc) * inv2;

    const float rm = expf(-thm * STEPF);
    const float rp = expf(-thp * STEPF);
    const float Lf = (float)L;
    const float SEm = (-expm1f(-thm * STEPF * Lf)) / (-expm1f(-thm * STEPF));
    const float SEp = (-expm1f(-thp * STEPF * Lf)) / (-expm1f(-thp * STEPF));

    const float cmv = 1.f - Te * thm;
    const float cpc = Te * thp - 1.f;
    const float inv_she = 1.f / (SEm - SEp);
    const float inv_shp = 1.f / fmaf(cmv, SEm, cpc * SEp);

    const float alpha = vp * inv_shp * cmv + ve * inv_she;
    const float beta  = vp * inv_shp * cpc - ve * inv_she;
    const float Kz    = -(0.00487f * 4.3f);
    const u64   ZAB   = pack2(Kz * alpha, Kz * beta);

    const float cosfa = 0.98480775301220806f;
    const float E1    = expf(-0.00487f);
    const float M0t   = 100.f * (1.f - cosfa * E1) / (1.f - E1);
    const float bse   = 100.f - M0t * (1.f - E1) / (1.f - E1 * cosfa);
    const float c0 = E1, c1 = E1, c2 = E1 * 0.5f, c3 = E1 * (1.f / 6.f);

    const u64 R = pack2(rm, rp);

    #define SIG_OF(Sv, dst) do {                                             \
        float _zl, _zh; unpack2(mul2((Sv), ZAB), _zl, _zh);                  \
        const float _z = _zl + _zh;                                          \
        const float _e = fmaf(fmaf(fmaf(_z, c3, c2), _z, c1), _z, c0);       \
        (dst) = fmaf(fmaf(-M0t, _e, M0t), rcpf(fmaf(-cosfa, _e, 1.f)), bse); \
    } while (0)

    float* optr = out + pix;
    const size_t stp = (size_t)npix;

    if (aligned) {
        const u64 ONE = pack2(1.f, 1.f);
        const u64 R2 = mul2(R, R), R6 = mul2(mul2(R2, R2), R2);
        u64 G6 = fma2(R, ONE, ONE);
        G6 = fma2(G6, R, ONE); G6 = fma2(G6, R, ONE);
        G6 = fma2(G6, R, ONE); G6 = fma2(G6, R, ONE);            // 1+r+..+r^5
        u64 H6 = fma2(R, ONE, pack2(2.f, 2.f));
        H6 = fma2(H6, R, pack2(3.f, 3.f)); H6 = fma2(H6, R, pack2(4.f, 4.f));
        H6 = fma2(H6, R, pack2(5.f, 5.f)); H6 = fma2(H6, R, pack2(6.f, 6.f)); // Σ i·r^(6-i)

        float sig0; SIG_OF(0ull, sig0);          // j=0..2: state & extra both 0
        optr[0] = sig0; optr[stp] = sig0; optr[2 * stp] = sig0;
        optr += 3 * stp;

        const u64* __restrict__ pp  = reinterpret_cast<const u64*>(s_p4);   // [2i]=Adup, [2i+1]=sldup
        const u64* __restrict__ exq = reinterpret_cast<const u64*>(s_ex);
        u64 dm = g_dmask >> 3;                    // bit 0 -> output j=3

        u64 S = pp[0] ;                           // dup'd aif[30] (A of piece 0)
        // take only the low-lane semantics: pp[0] is (A,A), exactly dup2(aif[30])

        const int npairs = ns - 4;
        for (int k = 0; k < npairs; ++k) {
            const u64 A0 = pp[4 * k + 0], L0 = pp[4 * k + 1];
            const u64 A1 = pp[4 * k + 2], L1 = pp[4 * k + 3];
            S = fma2(S, R6, fma2(L0, H6, mul2(A0, G6)));        // -> state at 12(k+3)
            u64 Se = S;
            if (dm & 1ull) Se = fma2(S, R, exq[k + 3]);         // d_j = 1: one extra step
            dm >>= 1;
            float sig; SIG_OF(Se, sig);
            *optr = sig; optr += stp;
            S = fma2(S, R6, fma2(L1, H6, mul2(A1, G6)));        // -> knot
        }
        const u64 An = pp[2 * (NP - 1)], Ln = pp[2 * (NP - 1) + 1];
        S = fma2(S, R6, fma2(Ln, H6, mul2(An, G6)));
        u64 Se = S;
        if (dm & 1ull) Se = fma2(S, R, exq[ns - 1]);
        float sigl; SIG_OF(Se, sigl);
        *optr = sigl;
    } else {
        u64 S = 0ull;
        int m = 0;
        for (int j = 0; j < ns; ++j) {
            const int target = s_idx[j];
            #pragma unroll 4
            for (; m <= target; ++m) S = fma2(S, R, dup2(s_aif[m]));
            float sig; SIG_OF(S, sig);
            *optr = sig; optr += stp;
        }
    }
    #undef SIG_OF
}

extern "C" void kernel_launch(void* const* d_in, const int* in_sizes, int n_in,
                              void* d_out, int out_size)
{
    const float* param       = (const float*)d_in[0];
    const float* sample_time = (const float*)d_in[1];
    const float* Cp          = (const float*)d_in[2];
    float* out = (float*)d_out;

    const int ns   = in_sizes[1];
    const int npix = in_sizes[0] / 4;

    dce_prep_kernel<<<1, 128>>>(sample_time, Cp, ns);
    dce_main_kernel<<<(npix + TPB - 1) / TPB, TPB>>>(param, out, npix, ns);
}